// round 9
// baseline (speedup 1.0000x reference)
#include <cuda_runtime.h>
#include <cstdint>
#include <cstddef>

#define BB 64
#define TT 512
#define AA 128
#define HH 512
#define G4 2048  // 4*H
#define NCTA 128

typedef unsigned long long ull;

// ---------------- scratch (static device allocations) ----------------
__device__ float g_pre[(size_t)TT * G4 * BB];   // 256MB: pre-gates [t][row][b]
__device__ float g_hall[(size_t)TT * BB * HH];  // 64MB : h history [t][b][H]
__device__ ull   g_hT2[2][(HH / 2) * BB];       // recurrent h, kpair-packed: [buf][kp*64+b]
__device__ float g_wp[(size_t)BB * AA * HH];    // 16MB : W'[b]
__device__ unsigned g_flag[NCTA];               // epoch flags (monotone)

__device__ __forceinline__ void st_rel(unsigned* p, unsigned v) {
    asm volatile("st.release.gpu.global.u32 [%0], %1;" :: "l"(p), "r"(v) : "memory");
}
__device__ __forceinline__ unsigned ld_acq(const unsigned* p) {
    unsigned v;
    asm volatile("ld.acquire.gpu.global.u32 %0, [%1];" : "=r"(v) : "l"(p) : "memory");
    return v;
}
__device__ __forceinline__ ull fma2(ull a, ull b, ull c) {
    ull d;
    asm("fma.rn.f32x2 %0, %1, %2, %3;" : "=l"(d) : "l"(a), "l"(b), "l"(c));
    return d;
}
__device__ __forceinline__ ull add2(ull a, ull b) {
    ull d;
    asm("add.rn.f32x2 %0, %1, %2;" : "=l"(d) : "l"(a), "l"(b));
    return d;
}
__device__ __forceinline__ float2 unpack2(ull v) {
    float lo, hi;
    asm("mov.b64 {%0, %1}, %2;" : "=f"(lo), "=f"(hi) : "l"(v));
    return make_float2(lo, hi);
}
__device__ __forceinline__ float fsigmoid(float x) {
    return __fdividef(1.0f, 1.0f + __expf(-x));
}
__device__ __forceinline__ float ftanh(float x) {
    return __fdividef(2.0f, 1.0f + __expf(-2.0f * x)) - 1.0f;
}

// ---------------- kernel 0: pack h0 into g_hT2[0] ----------------
__global__ void k_init(const float* __restrict__ h0) {
    int id = blockIdx.x * blockDim.x + threadIdx.x;   // 16384 = 256 kp x 64 b
    int kp = id >> 6, b = id & 63;
    float2 v = make_float2(h0[b * HH + 2 * kp], h0[b * HH + 2 * kp + 1]);
    ((float2*)g_hT2[0])[id] = v;
}

// ---------------- kernel 1: pre[t][row][b] (transposed store, f32x2) ----------------
__global__ __launch_bounds__(256) void k_pregates(const float* __restrict__ x,
                                                  const float* __restrict__ w_ih,
                                                  const float* __restrict__ b_ih,
                                                  const float* __restrict__ b_hh) {
    __shared__ float As[64][68];
    __shared__ float Bs[64][68];
    const int t  = blockIdx.y;
    const int n0 = blockIdx.x * 64;
    const int tid = threadIdx.x;
    const int tm = tid >> 4;
    const int tn = tid & 15;
    ull acc2[4][4] = {};

    for (int k0 = 0; k0 < AA; k0 += 64) {
#pragma unroll
        for (int i = 0; i < 4; i++) {
            int id = tid + i * 256;
            int r = id >> 4, c4 = (id & 15) << 2;
            *(float4*)&As[r][c4] = *(const float4*)&x[((size_t)r * TT + t) * AA + k0 + c4];
            *(float4*)&Bs[r][c4] = *(const float4*)&w_ih[(size_t)(n0 + r) * AA + k0 + c4];
        }
        __syncthreads();
#pragma unroll
        for (int k = 0; k < 64; k += 4) {
            ulonglong2 a[4], b[4];
#pragma unroll
            for (int i = 0; i < 4; i++) a[i] = *(const ulonglong2*)&As[tm * 4 + i][k];
#pragma unroll
            for (int j = 0; j < 4; j++) b[j] = *(const ulonglong2*)&Bs[tn * 4 + j][k];
#pragma unroll
            for (int i = 0; i < 4; i++)
#pragma unroll
                for (int j = 0; j < 4; j++) {
                    acc2[i][j] = fma2(a[i].x, b[j].x, acc2[i][j]);
                    acc2[i][j] = fma2(a[i].y, b[j].y, acc2[i][j]);
                }
        }
        __syncthreads();
    }
    float4 bi = *(const float4*)&b_ih[n0 + tn * 4];
    float4 bh = *(const float4*)&b_hh[n0 + tn * 4];
    float bias[4] = {bi.x + bh.x, bi.y + bh.y, bi.z + bh.z, bi.w + bh.w};
#pragma unroll
    for (int j = 0; j < 4; j++) {
        float r[4];
#pragma unroll
        for (int i = 0; i < 4; i++) {
            float2 u = unpack2(acc2[i][j]);
            r[i] = u.x + u.y + bias[j];
        }
        *(float4*)&g_pre[((size_t)t * G4 + n0 + tn * 4 + j) * BB + tm * 4] =
            make_float4(r[0], r[1], r[2], r[3]);
    }
}

// ---------------- kernel 2: W'[b] = w_out + w_out @ M[b] ----------------
__global__ __launch_bounds__(256) void k_wprime(const float* __restrict__ w_out,
                                                const float* __restrict__ Mm) {
    __shared__ float As[64][68];
    __shared__ float Bs[64][68];
    const int b  = blockIdx.z;
    const int m0 = blockIdx.y * 64;
    const int n0 = blockIdx.x * 64;
    const int tid = threadIdx.x;
    const int tm = tid >> 4, tn = tid & 15;
    float acc[4][4] = {};

    for (int k0 = 0; k0 < HH; k0 += 64) {
#pragma unroll
        for (int i = 0; i < 4; i++) {
            int id = tid + i * 256;
            int r = id >> 4, c4 = (id & 15) << 2;
            *(float4*)&As[r][c4] = *(const float4*)&w_out[(size_t)(m0 + r) * HH + k0 + c4];
            *(float4*)&Bs[r][c4] = *(const float4*)&Mm[((size_t)b * HH + k0 + r) * HH + n0 + c4];
        }
        __syncthreads();
#pragma unroll
        for (int k = 0; k < 64; k += 4) {
            float4 a[4];
#pragma unroll
            for (int i = 0; i < 4; i++) a[i] = *(const float4*)&As[tm * 4 + i][k];
#pragma unroll
            for (int kk = 0; kk < 4; kk++) {
                float4 bv = *(const float4*)&Bs[k + kk][tn * 4];
#pragma unroll
                for (int i = 0; i < 4; i++) {
                    float av = (kk == 0) ? a[i].x : (kk == 1) ? a[i].y : (kk == 2) ? a[i].z : a[i].w;
                    acc[i][0] += av * bv.x; acc[i][1] += av * bv.y;
                    acc[i][2] += av * bv.z; acc[i][3] += av * bv.w;
                }
            }
        }
        __syncthreads();
    }
#pragma unroll
    for (int i = 0; i < 4; i++) {
        int m = m0 + tm * 4 + i;
        float4 w0 = *(const float4*)&w_out[(size_t)m * HH + n0 + tn * 4];
        float4 v = make_float4(acc[i][0] + w0.x, acc[i][1] + w0.y,
                               acc[i][2] + w0.z, acc[i][3] + w0.w);
        *(float4*)&g_wp[((size_t)b * AA + m) * HH + n0 + tn * 4] = v;
    }
}

// ---------------- kernel 3: persistent recurrent loop (all 512 steps) ----------------
// 128 CTAs = 32 unit-groups x 4 batch-groups; 512 threads (16 warps).
// Warp-pair p (=ksg) depends on exactly 4 producer CTAs (jg=4p..4p+3): it polls
// only those flags, stages only its 4KB kp-slice, then a 64-thread named barrier.
// Removes the pre-GEMM global syncs; handoff latency overlaps across pairs.
__global__ __launch_bounds__(512) void k_loop(const float* __restrict__ w_hh,
                                              const float* __restrict__ c0) {
    extern __shared__ char smraw[];
    ull*        w2u   = (ull*)smraw;                   // [256 kp][64 slots]  131072 B
    ull*        hs2u  = (ull*)(smraw + 131072);        // [256 kp][16 b]      32768 B
    ull*        rbufU = (ull*)(smraw + 163840);        // [8 j][1032 ull]     66048 B
    ulonglong2* rbuf2 = (ulonglong2*)(smraw + 163840);

    const int tid = threadIdx.x;
    const int bid = blockIdx.x;
    const int jg  = bid & 31;        // unit group -> units j0..j0+15
    const int bgc = bid >> 5;        // batch group -> batches b0..b0+15
    const int j0  = jg * 16;
    const int b0  = bgc * 16;

    // ---- load w (kpair-packed, bank-interleaved slots) ----
    for (int idx = tid; idx < 64 * 256; idx += 512) {
        int rr = idx & 63, kp = idx >> 6;
        int gate = rr >> 4, ju = rr & 15;
        float2 wv = *(const float2*)(w_hh + (size_t)(gate * HH + j0 + ju) * HH + 2 * kp);
        ull v;
        asm("mov.b64 %0, {%1,%2};" : "=l"(v) : "f"(wv.x), "f"(wv.y));
        int rh = rr >> 5, rl = rr & 31;
        int slot = ((rl >> 1) & 1) * 16 + (rl >> 2) * 2 + (rl & 1);
        w2u[kp * 64 + rh * 32 + slot] = v;
    }

    // ---- GEMM mapping: warp = ksg*2 + rh; lane = rql*4 + bgl ----
    const int lane = tid & 31;
    const int warp = tid >> 5;
    const int ksg  = warp >> 1;      // warp-pair id 0..7 (32 kp each)
    const int rh   = warp & 1;       // row half (32 rows)
    const int rql  = lane >> 2;      // row quad 0..7
    const int bgl  = lane & 3;       // batch quad 0..3

    // producer flag this lane polls (lanes 0..3 only)
    const unsigned* poll_fp = &g_flag[bgc * 32 + 4 * ksg + (lane & 3)];

    // ---- finalize+pointwise mapping (tid < 256): thread owns (pb, pu) ----
    const int pb = tid & 15, pu = tid >> 4;   // valid for tid<256
    const bool pact = (tid < 256);
    float c_reg = 0.f;
    if (pact) c_reg = c0[(size_t)(b0 + pb) * HH + j0 + pu];
    const int hT_off = ((j0 + pu) >> 1) * 128 + (b0 + pb) * 2 + ((j0 + pu) & 1);
    const int fin_bgl = pb >> 2;
    const int fin_bp  = (pb >> 1) & 1;
    const int fin_par = pb & 1;

    const unsigned e0 = ld_acq(&g_flag[bid]);
    __syncthreads();

    for (int t = 0; t < TT; ++t) {
        // prefetch pre (static data; no dependence on flags)
        float pr[4];
        if (pact) {
#pragma unroll
            for (int g = 0; g < 4; g++)
                pr[g] = __ldg(&g_pre[((size_t)t * G4 + g * HH + j0 + pu) * BB + b0 + pb]);
        }

        // ---- per-pair dependency: poll only this pair's 4 producers ----
        if (t > 0) {
            if (lane < 4) {
                const unsigned target = e0 + (unsigned)t;
                while ((int)(ld_acq(poll_fp) - target) < 0) {}
            }
            __syncwarp();
        }
        const ulonglong2* hsrc = (const ulonglong2*)g_hT2[t & 1];

        // ---- stage this pair's 4KB kp-slice (both warps split it) ----
        {
            ulonglong2 v[4];
#pragma unroll
            for (int i = 0; i < 4; ++i) {
                int idx = lane + 32 * (i + 4 * rh);       // 0..255 within pair
                int kpl = idx >> 3, blp = idx & 7;
                v[i] = __ldcg(hsrc + (ksg * 32 + kpl) * 32 + bgc * 8 + blp);
            }
#pragma unroll
            for (int i = 0; i < 4; ++i) {
                int idx = lane + 32 * (i + 4 * rh);
                int kpl = idx >> 3, blp = idx & 7;
                *(ulonglong2*)(hs2u + (ksg * 32 + kpl) * 16 + blp * 2) = v[i];
            }
        }
        asm volatile("bar.sync %0, 64;" :: "r"(1 + ksg) : "memory");

        // ---- GEMM: 32 kp per thread, 16 fma2 per kp; all LDS conflict-free ----
        ull acc[4][4];
#pragma unroll
        for (int r = 0; r < 4; r++)
#pragma unroll
            for (int b = 0; b < 4; b++) acc[r][b] = 0ull;
        {
            const ull* hp = hs2u + (ksg * 32) * 16 + bgl * 4;
            const ull* wp = w2u + (size_t)(ksg * 32) * 64 + rh * 32 + rql * 2;
#pragma unroll 8
            for (int kp = 0; kp < 32; ++kp) {
                ulonglong2 h01 = *(const ulonglong2*)(hp + kp * 16);
                ulonglong2 h23 = *(const ulonglong2*)(hp + kp * 16 + 2);
                ulonglong2 w01 = *(const ulonglong2*)(wp + kp * 64);
                ulonglong2 w23 = *(const ulonglong2*)(wp + kp * 64 + 16);
                ull hv[4] = {h01.x, h01.y, h23.x, h23.y};
                ull wv[4] = {w01.x, w01.y, w23.x, w23.y};
#pragma unroll
                for (int r = 0; r < 4; r++)
#pragma unroll
                    for (int b = 0; b < 4; b++)
                        acc[r][b] = fma2(hv[b], wv[r], acc[r][b]);
            }
        }

        // ---- publish partials: rbuf2[j*516 + tid] ----
        {
            ulonglong2* rp = rbuf2 + tid;
#pragma unroll
            for (int r = 0; r < 4; r++)
#pragma unroll
                for (int bp = 0; bp < 2; bp++)
                    rp[(r * 2 + bp) * 516] = make_ulonglong2(acc[r][bp * 2], acc[r][bp * 2 + 1]);
        }
        __syncthreads();

        // ---- merged finalize + LSTM pointwise (tid < 256) ----
        if (pact) {
            float gv[4];
#pragma unroll
            for (int g = 0; g < 4; g++) {
                const int row  = g * 16 + pu;
                const int rhf  = row >> 5;
                const int rqlf = (row >> 2) & 7;
                const int ri   = row & 3;
                const int j    = ri * 2 + fin_bp;
                const ull* base = rbufU + (size_t)j * 1032 + rhf * 64 + rqlf * 8
                                  + fin_bgl * 2 + fin_par;
                ull s = base[0];
#pragma unroll
                for (int ks = 1; ks < 8; ++ks)
                    s = add2(s, base[ks * 128]);
                float2 u = unpack2(s);
                gv[g] = u.x + u.y + pr[g];
            }
            float si = fsigmoid(gv[0]);
            float sf = fsigmoid(gv[1]);
            float tg = ftanh(gv[2]);
            float so = fsigmoid(gv[3]);
            c_reg = sf * c_reg + si * tg;
            float hn = so * ftanh(c_reg);
            __stcg((float*)g_hT2[(t + 1) & 1] + hT_off, hn);
            // stash hn for post-release hall store via register (no extra smem)
            pr[0] = hn;
        }
        __syncthreads();
        if (tid == 0) st_rel(&g_flag[bid], e0 + (unsigned)(t + 1));
        if (pact)  // h history off the critical path (only k_out consumes it)
            __stcg(&g_hall[(size_t)t * BB * HH + (size_t)(b0 + pb) * HH + j0 + pu], pr[0]);
    }
}

// ---------------- kernel 4: out[b][t][a] = h_all[t][b] . W'[b][a] + b_out[a] (f32x2) ----
__global__ __launch_bounds__(256) void k_out(const float* __restrict__ b_out,
                                             float* __restrict__ out) {
    __shared__ float As[64][68];
    __shared__ float Bs[64][68];
    const int b  = blockIdx.z;
    const int m0 = blockIdx.y * 64;
    const int n0 = blockIdx.x * 64;
    const int tid = threadIdx.x;
    const int tm = tid >> 4, tn = tid & 15;
    ull acc2[4][4] = {};

    for (int k0 = 0; k0 < HH; k0 += 64) {
#pragma unroll
        for (int i = 0; i < 4; i++) {
            int id = tid + i * 256;
            int r = id >> 4, c4 = (id & 15) << 2;
            *(float4*)&As[r][c4] = *(const float4*)&g_hall[((size_t)(m0 + r) * BB + b) * HH + k0 + c4];
            *(float4*)&Bs[r][c4] = *(const float4*)&g_wp[((size_t)b * AA + n0 + r) * HH + k0 + c4];
        }
        __syncthreads();
#pragma unroll
        for (int k = 0; k < 64; k += 4) {
            ulonglong2 a[4], bv[4];
#pragma unroll
            for (int i = 0; i < 4; i++) a[i] = *(const ulonglong2*)&As[tm * 4 + i][k];
#pragma unroll
            for (int j = 0; j < 4; j++) bv[j] = *(const ulonglong2*)&Bs[tn * 4 + j][k];
#pragma unroll
            for (int i = 0; i < 4; i++)
#pragma unroll
                for (int j = 0; j < 4; j++) {
                    acc2[i][j] = fma2(a[i].x, bv[j].x, acc2[i][j]);
                    acc2[i][j] = fma2(a[i].y, bv[j].y, acc2[i][j]);
                }
        }
        __syncthreads();
    }
    float4 bo = *(const float4*)&b_out[n0 + tn * 4];
    float bb[4] = {bo.x, bo.y, bo.z, bo.w};
#pragma unroll
    for (int i = 0; i < 4; i++) {
        float r[4];
#pragma unroll
        for (int j = 0; j < 4; j++) {
            float2 u = unpack2(acc2[i][j]);
            r[j] = u.x + u.y + bb[j];
        }
        int m = m0 + tm * 4 + i;
        *(float4*)&out[((size_t)b * TT + m) * AA + n0 + tn * 4] =
            make_float4(r[0], r[1], r[2], r[3]);
    }
}

// ---------------- launch ----------------
extern "C" void kernel_launch(void* const* d_in, const int* in_sizes, int n_in,
                              void* d_out, int out_size) {
    const float* x     = (const float*)d_in[0];
    const float* w_ih  = (const float*)d_in[1];
    const float* w_hh  = (const float*)d_in[2];
    const float* b_ih  = (const float*)d_in[3];
    const float* b_hh  = (const float*)d_in[4];
    const float* Mm    = (const float*)d_in[5];
    const float* w_out = (const float*)d_in[6];
    const float* b_out = (const float*)d_in[7];
    const float* h0    = (const float*)d_in[8];
    const float* c0    = (const float*)d_in[9];
    float* out = (float*)d_out;

    const int loop_smem = 131072 + 32768 + 66048;  // 229888 B
    static int attr_done = 0;
    if (!attr_done) {
        cudaFuncSetAttribute(k_loop, cudaFuncAttributeMaxDynamicSharedMemorySize, loop_smem);
        attr_done = 1;
    }

    k_init<<<64, 256>>>(h0);
    k_pregates<<<dim3(G4 / 64, TT), 256>>>(x, w_ih, b_ih, b_hh);
    k_wprime<<<dim3(HH / 64, AA / 64, BB), 256>>>(w_out, Mm);

    k_loop<<<NCTA, 512, loop_smem>>>(w_hh, c0);

    k_out<<<dim3(AA / 64, TT / 64, BB), 256>>>(b_out, out);
}

// round 10
// speedup vs baseline: 1.0135x; 1.0135x over previous
#include <cuda_runtime.h>
#include <cstdint>
#include <cstddef>

#define BB 64
#define TT 512
#define AA 128
#define HH 512
#define G4 2048  // 4*H
#define NCTA 128

typedef unsigned long long ull;

// ---------------- scratch (static device allocations) ----------------
__device__ float g_pre[(size_t)TT * G4 * BB];   // 256MB: pre-gates [t][row][b]
__device__ float g_hall[(size_t)TT * BB * HH];  // 64MB : h history [t][b][H]
__device__ ull   g_hT2[2][(HH / 2) * BB];       // recurrent h, kpair-packed: [buf][kp*64+b]
__device__ float g_wp[(size_t)BB * AA * HH];    // 16MB : W'[b]
__device__ unsigned g_flag[NCTA];               // epoch flags (monotone)

__device__ __forceinline__ void st_rel(unsigned* p, unsigned v) {
    asm volatile("st.release.gpu.global.u32 [%0], %1;" :: "l"(p), "r"(v) : "memory");
}
__device__ __forceinline__ unsigned ld_acq(const unsigned* p) {
    unsigned v;
    asm volatile("ld.acquire.gpu.global.u32 %0, [%1];" : "=r"(v) : "l"(p) : "memory");
    return v;
}
__device__ __forceinline__ ull fma2(ull a, ull b, ull c) {
    ull d;
    asm("fma.rn.f32x2 %0, %1, %2, %3;" : "=l"(d) : "l"(a), "l"(b), "l"(c));
    return d;
}
__device__ __forceinline__ ull add2(ull a, ull b) {
    ull d;
    asm("add.rn.f32x2 %0, %1, %2;" : "=l"(d) : "l"(a), "l"(b));
    return d;
}
__device__ __forceinline__ float2 unpack2(ull v) {
    float lo, hi;
    asm("mov.b64 {%0, %1}, %2;" : "=f"(lo), "=f"(hi) : "l"(v));
    return make_float2(lo, hi);
}
__device__ __forceinline__ float fsigmoid(float x) {
    return __fdividef(1.0f, 1.0f + __expf(-x));
}
__device__ __forceinline__ float ftanh(float x) {
    return __fdividef(2.0f, 1.0f + __expf(-2.0f * x)) - 1.0f;
}

// ---------------- kernel 0: pack h0 into g_hT2[0] ----------------
__global__ void k_init(const float* __restrict__ h0) {
    int id = blockIdx.x * blockDim.x + threadIdx.x;   // 16384 = 256 kp x 64 b
    int kp = id >> 6, b = id & 63;
    float2 v = make_float2(h0[b * HH + 2 * kp], h0[b * HH + 2 * kp + 1]);
    ((float2*)g_hT2[0])[id] = v;
}

// ---------------- kernel 1: pre[t][row][b] (transposed store, f32x2) ----------------
__global__ __launch_bounds__(256) void k_pregates(const float* __restrict__ x,
                                                  const float* __restrict__ w_ih,
                                                  const float* __restrict__ b_ih,
                                                  const float* __restrict__ b_hh) {
    __shared__ float As[64][68];
    __shared__ float Bs[64][68];
    const int t  = blockIdx.y;
    const int n0 = blockIdx.x * 64;
    const int tid = threadIdx.x;
    const int tm = tid >> 4;
    const int tn = tid & 15;
    ull acc2[4][4] = {};

    for (int k0 = 0; k0 < AA; k0 += 64) {
#pragma unroll
        for (int i = 0; i < 4; i++) {
            int id = tid + i * 256;
            int r = id >> 4, c4 = (id & 15) << 2;
            *(float4*)&As[r][c4] = *(const float4*)&x[((size_t)r * TT + t) * AA + k0 + c4];
            *(float4*)&Bs[r][c4] = *(const float4*)&w_ih[(size_t)(n0 + r) * AA + k0 + c4];
        }
        __syncthreads();
#pragma unroll
        for (int k = 0; k < 64; k += 4) {
            ulonglong2 a[4], b[4];
#pragma unroll
            for (int i = 0; i < 4; i++) a[i] = *(const ulonglong2*)&As[tm * 4 + i][k];
#pragma unroll
            for (int j = 0; j < 4; j++) b[j] = *(const ulonglong2*)&Bs[tn * 4 + j][k];
#pragma unroll
            for (int i = 0; i < 4; i++)
#pragma unroll
                for (int j = 0; j < 4; j++) {
                    acc2[i][j] = fma2(a[i].x, b[j].x, acc2[i][j]);
                    acc2[i][j] = fma2(a[i].y, b[j].y, acc2[i][j]);
                }
        }
        __syncthreads();
    }
    float4 bi = *(const float4*)&b_ih[n0 + tn * 4];
    float4 bh = *(const float4*)&b_hh[n0 + tn * 4];
    float bias[4] = {bi.x + bh.x, bi.y + bh.y, bi.z + bh.z, bi.w + bh.w};
#pragma unroll
    for (int j = 0; j < 4; j++) {
        float r[4];
#pragma unroll
        for (int i = 0; i < 4; i++) {
            float2 u = unpack2(acc2[i][j]);
            r[i] = u.x + u.y + bias[j];
        }
        *(float4*)&g_pre[((size_t)t * G4 + n0 + tn * 4 + j) * BB + tm * 4] =
            make_float4(r[0], r[1], r[2], r[3]);
    }
}

// ---------------- kernel 2: W'[b] = w_out + w_out @ M[b] ----------------
__global__ __launch_bounds__(256) void k_wprime(const float* __restrict__ w_out,
                                                const float* __restrict__ Mm) {
    __shared__ float As[64][68];
    __shared__ float Bs[64][68];
    const int b  = blockIdx.z;
    const int m0 = blockIdx.y * 64;
    const int n0 = blockIdx.x * 64;
    const int tid = threadIdx.x;
    const int tm = tid >> 4, tn = tid & 15;
    float acc[4][4] = {};

    for (int k0 = 0; k0 < HH; k0 += 64) {
#pragma unroll
        for (int i = 0; i < 4; i++) {
            int id = tid + i * 256;
            int r = id >> 4, c4 = (id & 15) << 2;
            *(float4*)&As[r][c4] = *(const float4*)&w_out[(size_t)(m0 + r) * HH + k0 + c4];
            *(float4*)&Bs[r][c4] = *(const float4*)&Mm[((size_t)b * HH + k0 + r) * HH + n0 + c4];
        }
        __syncthreads();
#pragma unroll
        for (int k = 0; k < 64; k += 4) {
            float4 a[4];
#pragma unroll
            for (int i = 0; i < 4; i++) a[i] = *(const float4*)&As[tm * 4 + i][k];
#pragma unroll
            for (int kk = 0; kk < 4; kk++) {
                float4 bv = *(const float4*)&Bs[k + kk][tn * 4];
#pragma unroll
                for (int i = 0; i < 4; i++) {
                    float av = (kk == 0) ? a[i].x : (kk == 1) ? a[i].y : (kk == 2) ? a[i].z : a[i].w;
                    acc[i][0] += av * bv.x; acc[i][1] += av * bv.y;
                    acc[i][2] += av * bv.z; acc[i][3] += av * bv.w;
                }
            }
        }
        __syncthreads();
    }
#pragma unroll
    for (int i = 0; i < 4; i++) {
        int m = m0 + tm * 4 + i;
        float4 w0 = *(const float4*)&w_out[(size_t)m * HH + n0 + tn * 4];
        float4 v = make_float4(acc[i][0] + w0.x, acc[i][1] + w0.y,
                               acc[i][2] + w0.z, acc[i][3] + w0.w);
        *(float4*)&g_wp[((size_t)b * AA + m) * HH + n0 + tn * 4] = v;
    }
}

// ---------------- kernel 3: persistent recurrent loop (all 512 steps) ----------------
// R8 skeleton; 2 global syncs/step. Staging remapped so each thread depends on
// exactly ONE producer CTA (poll folded into staging); post-pointwise release
// gated by a 256-thread named barrier instead of a full-CTA sync.
__global__ __launch_bounds__(512) void k_loop(const float* __restrict__ w_hh,
                                              const float* __restrict__ c0) {
    extern __shared__ char smraw[];
    ull*        w2u   = (ull*)smraw;                   // [256 kp][64 slots]  131072 B
    ull*        hs2u  = (ull*)(smraw + 131072);        // [256 kp][16 b]      32768 B
    ull*        rbufU = (ull*)(smraw + 163840);        // [8 j][1032 ull]     66048 B
    ulonglong2* rbuf2 = (ulonglong2*)(smraw + 163840);

    const int tid = threadIdx.x;
    const int bid = blockIdx.x;
    const int jg  = bid & 31;        // unit group -> units j0..j0+15
    const int bgc = bid >> 5;        // batch group -> batches b0..b0+15
    const int j0  = jg * 16;
    const int b0  = bgc * 16;

    // ---- load w (kpair-packed, bank-interleaved slots) ----
    for (int idx = tid; idx < 64 * 256; idx += 512) {
        int rr = idx & 63, kp = idx >> 6;
        int gate = rr >> 4, ju = rr & 15;
        float2 wv = *(const float2*)(w_hh + (size_t)(gate * HH + j0 + ju) * HH + 2 * kp);
        ull v;
        asm("mov.b64 %0, {%1,%2};" : "=l"(v) : "f"(wv.x), "f"(wv.y));
        int rh = rr >> 5, rl = rr & 31;
        int slot = ((rl >> 1) & 1) * 16 + (rl >> 2) * 2 + (rl & 1);
        w2u[kp * 64 + rh * 32 + slot] = v;
    }

    // ---- GEMM mapping: warp = ksg*2 + rh; lane = rql*4 + bgl ----
    const int lane = tid & 31;
    const int warp = tid >> 5;
    const int ksg  = warp >> 1;      // 0..7 (32 kp each)
    const int rh   = warp & 1;       // row half (32 rows)
    const int rql  = lane >> 2;      // row quad 0..7
    const int bgl  = lane & 3;       // batch quad 0..3

    // ---- staging mapping: thread's 4 u2 slices come from ONE producer ----
    const int st_prod = tid >> 4;                       // producer jg 0..31
    const int st_base = st_prod * 64 + (tid & 15);      // u2 index base
    const unsigned* poll_fp = &g_flag[bgc * 32 + st_prod];

    // ---- finalize+pointwise mapping (tid < 256): thread owns (pb, pu) ----
    const int pb = tid & 15, pu = tid >> 4;   // valid for tid<256
    const bool pact = (tid < 256);
    float c_reg = 0.f;
    if (pact) c_reg = c0[(size_t)(b0 + pb) * HH + j0 + pu];
    const int hT_off = ((j0 + pu) >> 1) * 128 + (b0 + pb) * 2 + ((j0 + pu) & 1);
    const int fin_bgl = pb >> 2;
    const int fin_bp  = (pb >> 1) & 1;
    const int fin_par = pb & 1;

    const unsigned e0 = ld_acq(&g_flag[bid]);
    __syncthreads();

    for (int t = 0; t < TT; ++t) {
        // prefetch pre (static data; no dependence on flags)
        float pr[4];
        if (pact) {
#pragma unroll
            for (int g = 0; g < 4; g++)
                pr[g] = __ldg(&g_pre[((size_t)t * G4 + g * HH + j0 + pu) * BB + b0 + pb]);
        }

        // ---- poll THIS thread-group's single producer, then stage its slice ----
        if (t > 0) {
            if ((tid & 15) == 0) {
                const unsigned target = e0 + (unsigned)t;
                while ((int)(ld_acq(poll_fp) - target) < 0) {}
            }
            __syncwarp();
        }
        const ulonglong2* hsrc = (const ulonglong2*)g_hT2[t & 1];
        {
            ulonglong2 v[4];
#pragma unroll
            for (int i = 0; i < 4; ++i) {
                int idx2 = st_base + i * 16;
                int kp = idx2 >> 3, blp = idx2 & 7;
                v[i] = __ldcg(hsrc + kp * 32 + bgc * 8 + blp);
            }
#pragma unroll
            for (int i = 0; i < 4; ++i) {
                int idx2 = st_base + i * 16;
                ((ulonglong2*)hs2u)[idx2] = v[i];
            }
        }
        __syncthreads();                                  // sync A (GEMM entry)

        // ---- GEMM: 32 kp per thread, 16 fma2 per kp; all LDS conflict-free ----
        ull acc[4][4];
#pragma unroll
        for (int r = 0; r < 4; r++)
#pragma unroll
            for (int b = 0; b < 4; b++) acc[r][b] = 0ull;
        {
            const ull* hp = hs2u + (ksg * 32) * 16 + bgl * 4;
            const ull* wp = w2u + (size_t)(ksg * 32) * 64 + rh * 32 + rql * 2;
#pragma unroll 8
            for (int kp = 0; kp < 32; ++kp) {
                ulonglong2 h01 = *(const ulonglong2*)(hp + kp * 16);
                ulonglong2 h23 = *(const ulonglong2*)(hp + kp * 16 + 2);
                ulonglong2 w01 = *(const ulonglong2*)(wp + kp * 64);
                ulonglong2 w23 = *(const ulonglong2*)(wp + kp * 64 + 16);
                ull hv[4] = {h01.x, h01.y, h23.x, h23.y};
                ull wv[4] = {w01.x, w01.y, w23.x, w23.y};
#pragma unroll
                for (int r = 0; r < 4; r++)
#pragma unroll
                    for (int b = 0; b < 4; b++)
                        acc[r][b] = fma2(hv[b], wv[r], acc[r][b]);
            }
        }

        // ---- publish partials: rbuf2[j*516 + tid] ----
        {
            ulonglong2* rp = rbuf2 + tid;
#pragma unroll
            for (int r = 0; r < 4; r++)
#pragma unroll
                for (int bp = 0; bp < 2; bp++)
                    rp[(r * 2 + bp) * 516] = make_ulonglong2(acc[r][bp * 2], acc[r][bp * 2 + 1]);
        }
        __syncthreads();                                  // sync B (publish done)

        // ---- merged finalize + LSTM pointwise (warps 0-7 only) ----
        if (pact) {
            float gv[4];
#pragma unroll
            for (int g = 0; g < 4; g++) {
                const int row  = g * 16 + pu;
                const int rhf  = row >> 5;
                const int rqlf = (row >> 2) & 7;
                const int ri   = row & 3;
                const int j    = ri * 2 + fin_bp;
                const ull* base = rbufU + (size_t)j * 1032 + rhf * 64 + rqlf * 8
                                  + fin_bgl * 2 + fin_par;
                ull s = base[0];
#pragma unroll
                for (int ks = 1; ks < 8; ++ks)
                    s = add2(s, base[ks * 128]);
                float2 u = unpack2(s);
                gv[g] = u.x + u.y + pr[g];
            }
            float si = fsigmoid(gv[0]);
            float sf = fsigmoid(gv[1]);
            float tg = ftanh(gv[2]);
            float so = fsigmoid(gv[3]);
            c_reg = sf * c_reg + si * tg;
            float hn = so * ftanh(c_reg);
            __stcg((float*)g_hT2[(t + 1) & 1] + hT_off, hn);
            // release after only the 8 pointwise warps have stored (named barrier)
            asm volatile("bar.sync 1, 256;" ::: "memory");
            if (tid == 0) st_rel(&g_flag[bid], e0 + (unsigned)(t + 1));
            // h history off the critical path (only k_out consumes it)
            __stcg(&g_hall[(size_t)t * BB * HH + (size_t)(b0 + pb) * HH + j0 + pu], hn);
        }
        // warps 8-15 fall through directly to next-step poll+stage
    }
}

// ---------------- kernel 4: out[b][t][a] = h_all[t][b] . W'[b][a] + b_out[a] (f32x2) ----
__global__ __launch_bounds__(256) void k_out(const float* __restrict__ b_out,
                                             float* __restrict__ out) {
    __shared__ float As[64][68];
    __shared__ float Bs[64][68];
    const int b  = blockIdx.z;
    const int m0 = blockIdx.y * 64;
    const int n0 = blockIdx.x * 64;
    const int tid = threadIdx.x;
    const int tm = tid >> 4, tn = tid & 15;
    ull acc2[4][4] = {};

    for (int k0 = 0; k0 < HH; k0 += 64) {
#pragma unroll
        for (int i = 0; i < 4; i++) {
            int id = tid + i * 256;
            int r = id >> 4, c4 = (id & 15) << 2;
            *(float4*)&As[r][c4] = *(const float4*)&g_hall[((size_t)(m0 + r) * BB + b) * HH + k0 + c4];
            *(float4*)&Bs[r][c4] = *(const float4*)&g_wp[((size_t)b * AA + n0 + r) * HH + k0 + c4];
        }
        __syncthreads();
#pragma unroll
        for (int k = 0; k < 64; k += 4) {
            ulonglong2 a[4], bv[4];
#pragma unroll
            for (int i = 0; i < 4; i++) a[i] = *(const ulonglong2*)&As[tm * 4 + i][k];
#pragma unroll
            for (int j = 0; j < 4; j++) bv[j] = *(const ulonglong2*)&Bs[tn * 4 + j][k];
#pragma unroll
            for (int i = 0; i < 4; i++)
#pragma unroll
                for (int j = 0; j < 4; j++) {
                    acc2[i][j] = fma2(a[i].x, bv[j].x, acc2[i][j]);
                    acc2[i][j] = fma2(a[i].y, bv[j].y, acc2[i][j]);
                }
        }
        __syncthreads();
    }
    float4 bo = *(const float4*)&b_out[n0 + tn * 4];
    float bb[4] = {bo.x, bo.y, bo.z, bo.w};
#pragma unroll
    for (int i = 0; i < 4; i++) {
        float r[4];
#pragma unroll
        for (int j = 0; j < 4; j++) {
            float2 u = unpack2(acc2[i][j]);
            r[j] = u.x + u.y + bb[j];
        }
        int m = m0 + tm * 4 + i;
        *(float4*)&out[((size_t)b * TT + m) * AA + n0 + tn * 4] =
            make_float4(r[0], r[1], r[2], r[3]);
    }
}

// ---------------- launch ----------------
extern "C" void kernel_launch(void* const* d_in, const int* in_sizes, int n_in,
                              void* d_out, int out_size) {
    const float* x     = (const float*)d_in[0];
    const float* w_ih  = (const float*)d_in[1];
    const float* w_hh  = (const float*)d_in[2];
    const float* b_ih  = (const float*)d_in[3];
    const float* b_hh  = (const float*)d_in[4];
    const float* Mm    = (const float*)d_in[5];
    const float* w_out = (const float*)d_in[6];
    const float* b_out = (const float*)d_in[7];
    const float* h0    = (const float*)d_in[8];
    const float* c0    = (const float*)d_in[9];
    float* out = (float*)d_out;

    const int loop_smem = 131072 + 32768 + 66048;  // 229888 B
    static int attr_done = 0;
    if (!attr_done) {
        cudaFuncSetAttribute(k_loop, cudaFuncAttributeMaxDynamicSharedMemorySize, loop_smem);
        attr_done = 1;
    }

    k_init<<<64, 256>>>(h0);
    k_pregates<<<dim3(G4 / 64, TT), 256>>>(x, w_ih, b_ih, b_hh);
    k_wprime<<<dim3(HH / 64, AA / 64, BB), 256>>>(w_out, Mm);

    k_loop<<<NCTA, 512, loop_smem>>>(w_hh, c0);

    k_out<<<dim3(AA / 64, TT / 64, BB), 256>>>(b_out, out);
}

// round 11
// speedup vs baseline: 1.8223x; 1.7980x over previous
#include <cuda_runtime.h>
#include <cstdint>
#include <cstddef>

#define BB 64
#define TT 512
#define AA 128
#define HH 512
#define G4 2048  // 4*H
#define NCTA 128

typedef unsigned long long ull;

// ---------------- scratch (static device allocations) ----------------
__device__ float g_pre[(size_t)TT * G4 * BB];   // 256MB: pre-gates [t][row][b]
__device__ float g_hall[(size_t)TT * BB * HH];  // 64MB : h history [t][b][H]
__device__ ull   g_hT2[2][(HH / 2) * BB];       // recurrent h, kpair-packed: [buf][kp*64+b]
__device__ float g_wp[(size_t)BB * AA * HH];    // 16MB : W'[b]
__device__ unsigned g_flag[NCTA];               // epoch flags (monotone)

__device__ __forceinline__ void st_rel(unsigned* p, unsigned v) {
    asm volatile("st.release.gpu.global.u32 [%0], %1;" :: "l"(p), "r"(v) : "memory");
}
__device__ __forceinline__ unsigned ld_acq(const unsigned* p) {
    unsigned v;
    asm volatile("ld.acquire.gpu.global.u32 %0, [%1];" : "=r"(v) : "l"(p) : "memory");
    return v;
}
__device__ __forceinline__ ull fma2(ull a, ull b, ull c) {
    ull d;
    asm("fma.rn.f32x2 %0, %1, %2, %3;" : "=l"(d) : "l"(a), "l"(b), "l"(c));
    return d;
}
__device__ __forceinline__ ull add2(ull a, ull b) {
    ull d;
    asm("add.rn.f32x2 %0, %1, %2;" : "=l"(d) : "l"(a), "l"(b));
    return d;
}
__device__ __forceinline__ float2 unpack2(ull v) {
    float lo, hi;
    asm("mov.b64 {%0, %1}, %2;" : "=f"(lo), "=f"(hi) : "l"(v));
    return make_float2(lo, hi);
}
__device__ __forceinline__ float fsigmoid(float x) {
    return __fdividef(1.0f, 1.0f + __expf(-x));
}
__device__ __forceinline__ float ftanh(float x) {
    return __fdividef(2.0f, 1.0f + __expf(-2.0f * x)) - 1.0f;
}

// ---------------- kernel 1: merged prep = pregates + wprime + h0-pack ----------------
// 1D grid: blocks [0,16384) pregates, [16384,17408) wprime, [17408,17472) init.
// Inner code identical to the proven separate kernels; merging overlaps wave tails.
#define NB_PRE 16384
#define NB_WPR 1024
#define NB_INIT 64

__global__ __launch_bounds__(256) void k_prep(const float* __restrict__ x,
                                              const float* __restrict__ w_ih,
                                              const float* __restrict__ b_ih,
                                              const float* __restrict__ b_hh,
                                              const float* __restrict__ w_out,
                                              const float* __restrict__ Mm,
                                              const float* __restrict__ h0) {
    __shared__ float As[64][68];
    __shared__ float Bs[64][68];
    const int bidg = blockIdx.x;
    const int tid = threadIdx.x;

    if (bidg < NB_PRE) {
        // ---- pregates: pre[t][row][b] = bias[row] + x[b][t] . w_ih[row] ----
        const int t  = bidg >> 5;
        const int n0 = (bidg & 31) * 64;
        const int tm = tid >> 4;
        const int tn = tid & 15;
        ull acc2[4][4] = {};

        for (int k0 = 0; k0 < AA; k0 += 64) {
#pragma unroll
            for (int i = 0; i < 4; i++) {
                int id = tid + i * 256;
                int r = id >> 4, c4 = (id & 15) << 2;
                *(float4*)&As[r][c4] = *(const float4*)&x[((size_t)r * TT + t) * AA + k0 + c4];
                *(float4*)&Bs[r][c4] = *(const float4*)&w_ih[(size_t)(n0 + r) * AA + k0 + c4];
            }
            __syncthreads();
#pragma unroll
            for (int k = 0; k < 64; k += 4) {
                ulonglong2 a[4], b[4];
#pragma unroll
                for (int i = 0; i < 4; i++) a[i] = *(const ulonglong2*)&As[tm * 4 + i][k];
#pragma unroll
                for (int j = 0; j < 4; j++) b[j] = *(const ulonglong2*)&Bs[tn * 4 + j][k];
#pragma unroll
                for (int i = 0; i < 4; i++)
#pragma unroll
                    for (int j = 0; j < 4; j++) {
                        acc2[i][j] = fma2(a[i].x, b[j].x, acc2[i][j]);
                        acc2[i][j] = fma2(a[i].y, b[j].y, acc2[i][j]);
                    }
            }
            __syncthreads();
        }
        float4 bi = *(const float4*)&b_ih[n0 + tn * 4];
        float4 bh = *(const float4*)&b_hh[n0 + tn * 4];
        float bias[4] = {bi.x + bh.x, bi.y + bh.y, bi.z + bh.z, bi.w + bh.w};
#pragma unroll
        for (int j = 0; j < 4; j++) {
            float r[4];
#pragma unroll
            for (int i = 0; i < 4; i++) {
                float2 u = unpack2(acc2[i][j]);
                r[i] = u.x + u.y + bias[j];
            }
            *(float4*)&g_pre[((size_t)t * G4 + n0 + tn * 4 + j) * BB + tm * 4] =
                make_float4(r[0], r[1], r[2], r[3]);
        }
    } else if (bidg < NB_PRE + NB_WPR) {
        // ---- wprime: W'[b] = w_out + w_out @ M[b] ----
        const int q  = bidg - NB_PRE;
        const int n0 = (q & 7) * 64;
        const int m0 = ((q >> 3) & 1) * 64;
        const int b  = q >> 4;
        const int tm = tid >> 4, tn = tid & 15;
        float acc[4][4] = {};

        for (int k0 = 0; k0 < HH; k0 += 64) {
#pragma unroll
            for (int i = 0; i < 4; i++) {
                int id = tid + i * 256;
                int r = id >> 4, c4 = (id & 15) << 2;
                *(float4*)&As[r][c4] = *(const float4*)&w_out[(size_t)(m0 + r) * HH + k0 + c4];
                *(float4*)&Bs[r][c4] = *(const float4*)&Mm[((size_t)b * HH + k0 + r) * HH + n0 + c4];
            }
            __syncthreads();
#pragma unroll
            for (int k = 0; k < 64; k += 4) {
                float4 a[4];
#pragma unroll
                for (int i = 0; i < 4; i++) a[i] = *(const float4*)&As[tm * 4 + i][k];
#pragma unroll
                for (int kk = 0; kk < 4; kk++) {
                    float4 bv = *(const float4*)&Bs[k + kk][tn * 4];
#pragma unroll
                    for (int i = 0; i < 4; i++) {
                        float av = (kk == 0) ? a[i].x : (kk == 1) ? a[i].y : (kk == 2) ? a[i].z : a[i].w;
                        acc[i][0] += av * bv.x; acc[i][1] += av * bv.y;
                        acc[i][2] += av * bv.z; acc[i][3] += av * bv.w;
                    }
                }
            }
            __syncthreads();
        }
#pragma unroll
        for (int i = 0; i < 4; i++) {
            int m = m0 + tm * 4 + i;
            float4 w0 = *(const float4*)&w_out[(size_t)m * HH + n0 + tn * 4];
            float4 v = make_float4(acc[i][0] + w0.x, acc[i][1] + w0.y,
                                   acc[i][2] + w0.z, acc[i][3] + w0.w);
            *(float4*)&g_wp[((size_t)b * AA + m) * HH + n0 + tn * 4] = v;
        }
    } else {
        // ---- init: pack h0 into g_hT2[0] ----
        int id = (bidg - NB_PRE - NB_WPR) * 256 + tid;   // 0..16383
        int kp = id >> 6, b = id & 63;
        float2 v = make_float2(h0[b * HH + 2 * kp], h0[b * HH + 2 * kp + 1]);
        ((float2*)g_hT2[0])[id] = v;
    }
}

// ---------------- kernel 3: persistent recurrent loop (all 512 steps) ----------------
// R8 skeleton verbatim (proven sync structure); GEMM inner loop software-pipelined.
__global__ __launch_bounds__(512) void k_loop(const float* __restrict__ w_hh,
                                              const float* __restrict__ c0) {
    extern __shared__ char smraw[];
    ull*        w2u   = (ull*)smraw;                   // [256 kp][64 slots]  131072 B
    ull*        hs2u  = (ull*)(smraw + 131072);        // [256 kp][16 b]      32768 B
    ull*        rbufU = (ull*)(smraw + 163840);        // [8 j][1032 ull]     66048 B
    ulonglong2* rbuf2 = (ulonglong2*)(smraw + 163840);

    const int tid = threadIdx.x;
    const int bid = blockIdx.x;
    const int jg  = bid & 31;        // unit group -> units j0..j0+15
    const int bgc = bid >> 5;        // batch group -> batches b0..b0+15
    const int j0  = jg * 16;
    const int b0  = bgc * 16;

    // ---- load w (kpair-packed, bank-interleaved slots) ----
    for (int idx = tid; idx < 64 * 256; idx += 512) {
        int rr = idx & 63, kp = idx >> 6;
        int gate = rr >> 4, ju = rr & 15;
        float2 wv = *(const float2*)(w_hh + (size_t)(gate * HH + j0 + ju) * HH + 2 * kp);
        ull v;
        asm("mov.b64 %0, {%1,%2};" : "=l"(v) : "f"(wv.x), "f"(wv.y));
        int rh = rr >> 5, rl = rr & 31;
        int slot = ((rl >> 1) & 1) * 16 + (rl >> 2) * 2 + (rl & 1);
        w2u[kp * 64 + rh * 32 + slot] = v;
    }

    // ---- GEMM mapping: warp = ksg*2 + rh; lane = rql*4 + bgl ----
    const int lane = tid & 31;
    const int warp = tid >> 5;
    const int ksg  = warp >> 1;      // 0..7 (32 kp each)
    const int rh   = warp & 1;       // row half (32 rows)
    const int rql  = lane >> 2;      // row quad 0..7
    const int bgl  = lane & 3;       // batch quad 0..3

    // ---- finalize+pointwise mapping (tid < 256): thread owns (pb, pu) ----
    const int pb = tid & 15, pu = tid >> 4;   // valid for tid<256
    const bool pact = (tid < 256);
    float c_reg = 0.f;
    if (pact) c_reg = c0[(size_t)(b0 + pb) * HH + j0 + pu];
    const int hT_off = ((j0 + pu) >> 1) * 128 + (b0 + pb) * 2 + ((j0 + pu) & 1);
    const int fin_bgl = pb >> 2;
    const int fin_bp  = (pb >> 1) & 1;
    const int fin_par = pb & 1;

    const unsigned e0 = ld_acq(&g_flag[bid]);
    __syncthreads();

    for (int t = 0; t < TT; ++t) {
        if (t > 0) {   // warp 0 polls all 32 domain flags; others sleep at barrier
            if (tid < 32) {
                const unsigned target = e0 + (unsigned)t;
                const unsigned* fp = &g_flag[bgc * 32 + tid];
                while ((int)(ld_acq(fp) - target) < 0) {}
            }
            __syncthreads();
        }
        const ulonglong2* hsrc = (const ulonglong2*)g_hT2[t & 1];

        // prefetch pre (static data; hidden behind GEMM)
        float pr[4];
        if (pact) {
#pragma unroll
            for (int g = 0; g < 4; g++)
                pr[g] = __ldg(&g_pre[((size_t)t * G4 + g * HH + j0 + pu) * BB + b0 + pb]);
        }

        // ---- stage h slice (32 KB): 4x LDG.128 -> STS.128, coalesced ----
        {
            ulonglong2 v[4];
#pragma unroll
            for (int i = 0; i < 4; ++i) {
                int idx2 = tid + i * 512;                 // 0..2047
                int kp = idx2 >> 3, blp = idx2 & 7;
                v[i] = __ldcg(hsrc + kp * 32 + bgc * 8 + blp);
            }
#pragma unroll
            for (int i = 0; i < 4; ++i) {
                int idx2 = tid + i * 512;
                int kp = idx2 >> 3, blp = idx2 & 7;
                *(ulonglong2*)(hs2u + kp * 16 + blp * 2) = v[i];
            }
        }
        __syncthreads();

        // ---- GEMM: 32 kp per thread, software-pipelined (rotate prefetch) ----
        ull acc[4][4];
#pragma unroll
        for (int r = 0; r < 4; r++)
#pragma unroll
            for (int b = 0; b < 4; b++) acc[r][b] = 0ull;
        {
            const ull* hp = hs2u + (ksg * 32) * 16 + bgl * 4;
            const ull* wp = w2u + (size_t)(ksg * 32) * 64 + rh * 32 + rql * 2;
            ulonglong2 h01 = *(const ulonglong2*)(hp);
            ulonglong2 h23 = *(const ulonglong2*)(hp + 2);
            ulonglong2 w01 = *(const ulonglong2*)(wp);
            ulonglong2 w23 = *(const ulonglong2*)(wp + 16);
#pragma unroll 8
            for (int kp = 0; kp < 32; ++kp) {
                ulonglong2 nh01, nh23, nw01, nw23;
                if (kp < 31) {
                    nh01 = *(const ulonglong2*)(hp + (kp + 1) * 16);
                    nh23 = *(const ulonglong2*)(hp + (kp + 1) * 16 + 2);
                    nw01 = *(const ulonglong2*)(wp + (kp + 1) * 64);
                    nw23 = *(const ulonglong2*)(wp + (kp + 1) * 64 + 16);
                }
                ull hv[4] = {h01.x, h01.y, h23.x, h23.y};
                ull wv[4] = {w01.x, w01.y, w23.x, w23.y};
#pragma unroll
                for (int r = 0; r < 4; r++)
#pragma unroll
                    for (int b = 0; b < 4; b++)
                        acc[r][b] = fma2(hv[b], wv[r], acc[r][b]);
                h01 = nh01; h23 = nh23; w01 = nw01; w23 = nw23;
            }
        }

        // ---- publish partials: rbuf2[j*516 + tid] ----
        {
            ulonglong2* rp = rbuf2 + tid;
#pragma unroll
            for (int r = 0; r < 4; r++)
#pragma unroll
                for (int bp = 0; bp < 2; bp++)
                    rp[(r * 2 + bp) * 516] = make_ulonglong2(acc[r][bp * 2], acc[r][bp * 2 + 1]);
        }
        __syncthreads();

        // ---- merged finalize + LSTM pointwise (tid < 256) ----
        float hn = 0.f;
        if (pact) {
            float gv[4];
#pragma unroll
            for (int g = 0; g < 4; g++) {
                const int row  = g * 16 + pu;
                const int rhf  = row >> 5;
                const int rqlf = (row >> 2) & 7;
                const int ri   = row & 3;
                const int j    = ri * 2 + fin_bp;
                const ull* base = rbufU + (size_t)j * 1032 + rhf * 64 + rqlf * 8
                                  + fin_bgl * 2 + fin_par;
                ull s = base[0];
#pragma unroll
                for (int ks = 1; ks < 8; ++ks)
                    s = add2(s, base[ks * 128]);
                float2 u = unpack2(s);
                gv[g] = u.x + u.y + pr[g];
            }
            float si = fsigmoid(gv[0]);
            float sf = fsigmoid(gv[1]);
            float tg = ftanh(gv[2]);
            float so = fsigmoid(gv[3]);
            c_reg = sf * c_reg + si * tg;
            hn = so * ftanh(c_reg);
            __stcg((float*)g_hT2[(t + 1) & 1] + hT_off, hn);
        }
        __syncthreads();
        if (tid == 0) st_rel(&g_flag[bid], e0 + (unsigned)(t + 1));
        if (pact)  // h history off the critical path (only k_out consumes it)
            __stcg(&g_hall[(size_t)t * BB * HH + (size_t)(b0 + pb) * HH + j0 + pu], hn);
    }
}

// ---------------- kernel 4: out[b][t][a] = h_all[t][b] . W'[b][a] + b_out[a] (f32x2) ----
__global__ __launch_bounds__(256) void k_out(const float* __restrict__ b_out,
                                             float* __restrict__ out) {
    __shared__ float As[64][68];
    __shared__ float Bs[64][68];
    const int b  = blockIdx.z;
    const int m0 = blockIdx.y * 64;
    const int n0 = blockIdx.x * 64;
    const int tid = threadIdx.x;
    const int tm = tid >> 4, tn = tid & 15;
    ull acc2[4][4] = {};

    for (int k0 = 0; k0 < HH; k0 += 64) {
#pragma unroll
        for (int i = 0; i < 4; i++) {
            int id = tid + i * 256;
            int r = id >> 4, c4 = (id & 15) << 2;
            *(float4*)&As[r][c4] = *(const float4*)&g_hall[((size_t)(m0 + r) * BB + b) * HH + k0 + c4];
            *(float4*)&Bs[r][c4] = *(const float4*)&g_wp[((size_t)b * AA + n0 + r) * HH + k0 + c4];
        }
        __syncthreads();
#pragma unroll
        for (int k = 0; k < 64; k += 4) {
            ulonglong2 a[4], bv[4];
#pragma unroll
            for (int i = 0; i < 4; i++) a[i] = *(const ulonglong2*)&As[tm * 4 + i][k];
#pragma unroll
            for (int j = 0; j < 4; j++) bv[j] = *(const ulonglong2*)&Bs[tn * 4 + j][k];
#pragma unroll
            for (int i = 0; i < 4; i++)
#pragma unroll
                for (int j = 0; j < 4; j++) {
                    acc2[i][j] = fma2(a[i].x, bv[j].x, acc2[i][j]);
                    acc2[i][j] = fma2(a[i].y, bv[j].y, acc2[i][j]);
                }
        }
        __syncthreads();
    }
    float4 bo = *(const float4*)&b_out[n0 + tn * 4];
    float bb[4] = {bo.x, bo.y, bo.z, bo.w};
#pragma unroll
    for (int i = 0; i < 4; i++) {
        float r[4];
#pragma unroll
        for (int j = 0; j < 4; j++) {
            float2 u = unpack2(acc2[i][j]);
            r[j] = u.x + u.y + bb[j];
        }
        int m = m0 + tm * 4 + i;
        *(float4*)&out[((size_t)b * TT + m) * AA + n0 + tn * 4] =
            make_float4(r[0], r[1], r[2], r[3]);
    }
}

// ---------------- launch ----------------
extern "C" void kernel_launch(void* const* d_in, const int* in_sizes, int n_in,
                              void* d_out, int out_size) {
    const float* x     = (const float*)d_in[0];
    const float* w_ih  = (const float*)d_in[1];
    const float* w_hh  = (const float*)d_in[2];
    const float* b_ih  = (const float*)d_in[3];
    const float* b_hh  = (const float*)d_in[4];
    const float* Mm    = (const float*)d_in[5];
    const float* w_out = (const float*)d_in[6];
    const float* b_out = (const float*)d_in[7];
    const float* h0    = (const float*)d_in[8];
    const float* c0    = (const float*)d_in[9];
    float* out = (float*)d_out;

    const int loop_smem = 131072 + 32768 + 66048;  // 229888 B
    static int attr_done = 0;
    if (!attr_done) {
        cudaFuncSetAttribute(k_loop, cudaFuncAttributeMaxDynamicSharedMemorySize, loop_smem);
        attr_done = 1;
    }

    k_prep<<<NB_PRE + NB_WPR + NB_INIT, 256>>>(x, w_ih, b_ih, b_hh, w_out, Mm, h0);
    k_loop<<<NCTA, 512, loop_smem>>>(w_hh, c0);
    k_out<<<dim3(AA / 64, TT / 64, BB), 256>>>(b_out, out);
}